// round 1
// baseline (speedup 1.0000x reference)
#include <cuda_runtime.h>
#include <cuda_bf16.h>
#include <math.h>

// Problem constants (fixed by the reference setup)
#define BATCH    32
#define SRC_LEN  2048
#define DIM      1024            // enc feature dim == dec_hid_dim
#define WARPS_PER_BLOCK 8
#define BLOCK_THREADS   (WARPS_PER_BLOCK * 32)

// Scratch for per-batch decoder contribution (alloc-free rule: __device__ global)
__device__ float g_edec[BATCH];

// ---------------------------------------------------------------------------
// Kernel 1: e_dec[b] = dec_hidden[b,:] . W[0, 0:1024] + bias
// One warp per batch element. 32 warps = 1 block of 1024 threads.
// ---------------------------------------------------------------------------
__global__ void edec_kernel(const float* __restrict__ dec_hidden,
                            const float* __restrict__ W,
                            const float* __restrict__ bias)
{
    int warp = threadIdx.x >> 5;
    int lane = threadIdx.x & 31;
    if (warp >= BATCH) return;

    const float4* row = reinterpret_cast<const float4*>(dec_hidden + (size_t)warp * DIM);
    const float4* wd  = reinterpret_cast<const float4*>(W);  // first 1024 floats = w_dec

    float acc = 0.f;
#pragma unroll
    for (int i = 0; i < DIM / 4 / 32; ++i) {   // 8 iterations
        float4 v = row[lane + i * 32];
        float4 w = wd [lane + i * 32];
        acc += v.x * w.x + v.y * w.y + v.z * w.z + v.w * w.w;
    }
#pragma unroll
    for (int o = 16; o > 0; o >>= 1)
        acc += __shfl_xor_sync(0xFFFFFFFFu, acc, o);

    if (lane == 0)
        g_edec[warp] = acc + bias[0];
}

// ---------------------------------------------------------------------------
// Kernel 2: out[b, s] = tanh( enc_outputs[s,b,:] . w_enc + e_dec[b] )
// One warp per (s,b) pair; row of 1024 floats is contiguous in gmem.
// w_enc staged in shared memory once per block.
// ---------------------------------------------------------------------------
__global__ void __launch_bounds__(BLOCK_THREADS)
score_kernel(const float* __restrict__ enc_outputs,
             const float* __restrict__ W,
             float* __restrict__ out)
{
    __shared__ float4 s_wenc[DIM / 4];   // 4 KB

    // Cooperative load of w_enc = W[0, 1024:2048]
    const float4* we_g = reinterpret_cast<const float4*>(W + DIM);
    for (int i = threadIdx.x; i < DIM / 4; i += BLOCK_THREADS)
        s_wenc[i] = we_g[i];
    __syncthreads();

    int warp = threadIdx.x >> 5;
    int lane = threadIdx.x & 31;
    int flat = blockIdx.x * WARPS_PER_BLOCK + warp;   // 0 .. SRC_LEN*BATCH-1
    int s = flat >> 5;        // flat / 32
    int b = flat & 31;        // flat % 32  (enc layout: [s][b][e])

    const float4* row = reinterpret_cast<const float4*>(
        enc_outputs + ((size_t)flat) * DIM);          // flat == s*32+b exactly

    float acc = 0.f;
#pragma unroll
    for (int i = 0; i < DIM / 4 / 32; ++i) {          // 8 independent float4 loads
        float4 v = row[lane + i * 32];
        float4 w = s_wenc[lane + i * 32];
        acc += v.x * w.x + v.y * w.y + v.z * w.z + v.w * w.w;
    }
#pragma unroll
    for (int o = 16; o > 0; o >>= 1)
        acc += __shfl_xor_sync(0xFFFFFFFFu, acc, o);

    if (lane == 0)
        out[(size_t)b * SRC_LEN + s] = tanhf(acc + g_edec[b]);
}

// ---------------------------------------------------------------------------
// Kernel 3: in-place row softmax over s (row length 2048), one block per b.
// ---------------------------------------------------------------------------
#define SM_THREADS 256
#define SM_VPT     (SRC_LEN / SM_THREADS)   // 8 values per thread

__global__ void __launch_bounds__(SM_THREADS)
softmax_kernel(float* __restrict__ out)
{
    __shared__ float red[SM_THREADS / 32];

    float* row = out + (size_t)blockIdx.x * SRC_LEN;
    int tid  = threadIdx.x;
    int lane = tid & 31;
    int warp = tid >> 5;

    float v[SM_VPT];
    float m = -INFINITY;
#pragma unroll
    for (int i = 0; i < SM_VPT; ++i) {
        v[i] = row[tid + i * SM_THREADS];
        m = fmaxf(m, v[i]);
    }
    // block max
#pragma unroll
    for (int o = 16; o > 0; o >>= 1)
        m = fmaxf(m, __shfl_xor_sync(0xFFFFFFFFu, m, o));
    if (lane == 0) red[warp] = m;
    __syncthreads();
    if (warp == 0) {
        float t = (lane < SM_THREADS / 32) ? red[lane] : -INFINITY;
#pragma unroll
        for (int o = 16; o > 0; o >>= 1)
            t = fmaxf(t, __shfl_xor_sync(0xFFFFFFFFu, t, o));
        if (lane == 0) red[0] = t;
    }
    __syncthreads();
    m = red[0];
    __syncthreads();

    float sum = 0.f;
#pragma unroll
    for (int i = 0; i < SM_VPT; ++i) {
        v[i] = __expf(v[i] - m);
        sum += v[i];
    }
    // block sum
#pragma unroll
    for (int o = 16; o > 0; o >>= 1)
        sum += __shfl_xor_sync(0xFFFFFFFFu, sum, o);
    if (lane == 0) red[warp] = sum;
    __syncthreads();
    if (warp == 0) {
        float t = (lane < SM_THREADS / 32) ? red[lane] : 0.f;
#pragma unroll
        for (int o = 16; o > 0; o >>= 1)
            t += __shfl_xor_sync(0xFFFFFFFFu, t, o);
        if (lane == 0) red[0] = t;
    }
    __syncthreads();
    float inv = 1.0f / red[0];

#pragma unroll
    for (int i = 0; i < SM_VPT; ++i)
        row[tid + i * SM_THREADS] = v[i] * inv;
}

// ---------------------------------------------------------------------------
extern "C" void kernel_launch(void* const* d_in, const int* in_sizes, int n_in,
                              void* d_out, int out_size)
{
    const float* dec_hidden  = (const float*)d_in[0];   // (32, 1024)
    const float* enc_outputs = (const float*)d_in[1];   // (2048, 32, 1024)
    const float* W           = (const float*)d_in[2];   // (1, 2048)
    const float* bias        = (const float*)d_in[3];   // (1,)
    float* out = (float*)d_out;                          // (32, 2048)

    edec_kernel<<<1, 1024>>>(dec_hidden, W, bias);

    int total_warps = SRC_LEN * BATCH;                  // 65536
    int blocks = total_warps / WARPS_PER_BLOCK;         // 8192
    score_kernel<<<blocks, BLOCK_THREADS>>>(enc_outputs, W, out);

    softmax_kernel<<<BATCH, SM_THREADS>>>(out);
}